// round 3
// baseline (speedup 1.0000x reference)
#include <cuda_runtime.h>

#define NN 50000
#define EE 800000
#define SB 256
#define NBLK ((NN + SB - 1) / SB)   // 196

// ---------------- device scratch (static allocation only, per harness rules) ----------------
__device__ int    d_is64;
__device__ int    d_cnt[NN];
__device__ int    d_cursor[NN];
__device__ int    d_rowptr[NN + 1];
__device__ int    d_col[EE];
__device__ int    d_bsum[SB];
__device__ float4 d_agg4[NN * 32];   // [NN,128] as float4
__device__ float4 d_h1_4[NN * 32];   // [NN,128]
__device__ float4 d_h2_4[NN * 16];   // [NN,64]
__device__ float4 d_y_4[NN * 16];    // [NN,64]

// ---------------- edge-index dtype probe ----------------
// If edge_index is int64 (little-endian), the high word of every element is 0
// (values in [0, 50000)). If int32, odd words are independent node ids.
__global__ void k_probe(const int* __restrict__ ei) {
    __shared__ int nonzero;
    if (threadIdx.x == 0) nonzero = 0;
    __syncthreads();
    for (int i = threadIdx.x; i < 4096; i += blockDim.x) {
        if (ei[2 * i + 1] != 0) nonzero = 1;
    }
    __syncthreads();
    if (threadIdx.x == 0) d_is64 = (nonzero == 0) ? 1 : 0;
}

__device__ __forceinline__ int edge_id(const void* ei, int which, int e) {
    if (d_is64) return (int)((const long long*)ei)[(size_t)which * EE + e];
    return ((const int*)ei)[(size_t)which * EE + e];
}

// ---------------- CSR build ----------------
__global__ void k_zero() {
    int i = blockIdx.x * blockDim.x + threadIdx.x;
    if (i < NN) { d_cnt[i] = 0; d_cursor[i] = 0; }
}

__global__ void k_count(const void* __restrict__ ei) {
    int e = blockIdx.x * blockDim.x + threadIdx.x;
    if (e < EE) {
        int d = edge_id(ei, 1, e);
        atomicAdd(&d_cnt[d], 1);
    }
}

__global__ void k_scan1() {
    __shared__ int s[SB];
    int tid = threadIdx.x;
    int i = blockIdx.x * SB + tid;
    int v = (i < NN) ? d_cnt[i] : 0;
    s[tid] = v;
    __syncthreads();
    for (int off = 1; off < SB; off <<= 1) {
        int t = (tid >= off) ? s[tid - off] : 0;
        __syncthreads();
        s[tid] += t;
        __syncthreads();
    }
    if (i < NN) d_rowptr[i] = s[tid] - v;           // exclusive
    if (tid == SB - 1) d_bsum[blockIdx.x] = s[tid]; // block total
}

__global__ void k_scan2() {
    __shared__ int s[SB];
    int tid = threadIdx.x;
    int v = (tid < NBLK) ? d_bsum[tid] : 0;
    s[tid] = v;
    __syncthreads();
    for (int off = 1; off < SB; off <<= 1) {
        int t = (tid >= off) ? s[tid - off] : 0;
        __syncthreads();
        s[tid] += t;
        __syncthreads();
    }
    if (tid < NBLK) d_bsum[tid] = s[tid] - v;       // exclusive
}

__global__ void k_scan3() {
    int tid = threadIdx.x;
    int i = blockIdx.x * SB + tid;
    if (i < NN) d_rowptr[i] += d_bsum[blockIdx.x];
    if (i == 0) d_rowptr[NN] = EE;
}

__global__ void k_fill(const void* __restrict__ ei) {
    int e = blockIdx.x * blockDim.x + threadIdx.x;
    if (e < EE) {
        int d = edge_id(ei, 1, e);
        int s = edge_id(ei, 0, e);
        int p = atomicAdd(&d_cursor[d], 1);
        d_col[d_rowptr[d] + p] = s;
    }
}

// ---------------- neighbor mean aggregation (128 features, warp per node) ----------------
// use_h1 == 0 : read from xext (harness input x); use_h1 == 1 : read from d_h1_4
__global__ void k_agg_mean(const float* xext, int use_h1) {
    const float4* x4 = use_h1 ? (const float4*)d_h1_4 : (const float4*)xext;
    int idx = blockIdx.x * blockDim.x + threadIdx.x;
    int node = idx >> 5;
    int lane = idx & 31;
    if (node >= NN) return;
    int beg = d_rowptr[node], end = d_rowptr[node + 1];
    float4 acc = make_float4(0.f, 0.f, 0.f, 0.f);
    for (int j = beg; j < end; j++) {
        int s = d_col[j];
        float4 v = x4[(size_t)s * 32 + lane];
        acc.x += v.x; acc.y += v.y; acc.z += v.z; acc.w += v.w;
    }
    int c = end - beg;
    float inv = 1.0f / (float)(c > 0 ? c : 1);
    acc.x *= inv; acc.y *= inv; acc.z *= inv; acc.w *= inv;
    d_agg4[(size_t)node * 32 + lane] = acc;
}

// ---------------- layer1 GEMM: h1 = relu(agg @ W1l + x @ W1r + b1l) ----------------
// virtual K = 256 (128 from agg@W1l + 128 from x@W1r). BM=64, BN=128, 256 threads,
// micro-tile 8 rows x 4 cols per thread.
__global__ void __launch_bounds__(256) k_gemm_relu128(
    const float* __restrict__ x,
    const float* __restrict__ W1, const float* __restrict__ W2,
    const float* __restrict__ bias)
{
    __shared__ float As[64][17];
    __shared__ float Ws[16][128];
    int tid = threadIdx.x;
    int rowBase = blockIdx.x * 64;
    int rg = tid >> 5;   // warp id 0..7 -> rows rg*8..+7
    int cg = tid & 31;   // lane -> cols cg*4..+3
    float acc[8][4];
#pragma unroll
    for (int i = 0; i < 8; i++)
#pragma unroll
        for (int j = 0; j < 4; j++) acc[i][j] = 0.f;

    int lr = tid >> 2;
    int lc = (tid & 3) * 4;
    bool lvalid = (rowBase + lr) < NN;

    for (int kk = 0; kk < 256; kk += 16) {
        const float* A = (kk < 128) ? (const float*)d_agg4 : x;
        const float* W = (kk < 128) ? W1 : W2;
        int k0 = kk & 127;
        float4 va = make_float4(0.f, 0.f, 0.f, 0.f);
        if (lvalid) va = *(const float4*)(A + (size_t)(rowBase + lr) * 128 + k0 + lc);
        As[lr][lc + 0] = va.x; As[lr][lc + 1] = va.y;
        As[lr][lc + 2] = va.z; As[lr][lc + 3] = va.w;
#pragma unroll
        for (int it = 0; it < 2; it++) {
            int idx = tid + it * 256;
            int wr = idx >> 5;
            int wc = (idx & 31) * 4;
            *(float4*)&Ws[wr][wc] = *(const float4*)(W + (size_t)(k0 + wr) * 128 + wc);
        }
        __syncthreads();
#pragma unroll
        for (int k = 0; k < 16; k++) {
            float4 bv = *(const float4*)&Ws[k][cg * 4];
#pragma unroll
            for (int i = 0; i < 8; i++) {
                float a = As[rg * 8 + i][k];
                acc[i][0] += a * bv.x;
                acc[i][1] += a * bv.y;
                acc[i][2] += a * bv.z;
                acc[i][3] += a * bv.w;
            }
        }
        __syncthreads();
    }
    float4 bb = *(const float4*)(bias + cg * 4);
#pragma unroll
    for (int i = 0; i < 8; i++) {
        int r = rowBase + rg * 8 + i;
        if (r < NN) {
            float4 v;
            v.x = fmaxf(acc[i][0] + bb.x, 0.f);
            v.y = fmaxf(acc[i][1] + bb.y, 0.f);
            v.z = fmaxf(acc[i][2] + bb.z, 0.f);
            v.w = fmaxf(acc[i][3] + bb.w, 0.f);
            *((float4*)d_h1_4 + (size_t)r * 32 + cg) = v;
        }
    }
}

// ---------------- layer2 GEMM: h2 = agg2 @ W2l + h1 @ W2r + b2l (no activation) ----------
// virtual K = 256, BM=64, BN=64, 256 threads, micro-tile 4x4.
__global__ void __launch_bounds__(256) k_gemm_64(
    const float* __restrict__ W1, const float* __restrict__ W2,
    const float* __restrict__ bias)
{
    __shared__ float As[64][17];
    __shared__ float Ws[16][64];
    int tid = threadIdx.x;
    int rowBase = blockIdx.x * 64;
    int rg = tid >> 4;   // 0..15 -> rows rg*4
    int cg = tid & 15;   // cols cg*4
    float acc[4][4];
#pragma unroll
    for (int i = 0; i < 4; i++)
#pragma unroll
        for (int j = 0; j < 4; j++) acc[i][j] = 0.f;

    int lr = tid >> 2;
    int lc = (tid & 3) * 4;
    bool lvalid = (rowBase + lr) < NN;

    for (int kk = 0; kk < 256; kk += 16) {
        const float* A = (kk < 128) ? (const float*)d_agg4 : (const float*)d_h1_4;
        const float* W = (kk < 128) ? W1 : W2;
        int k0 = kk & 127;
        float4 va = make_float4(0.f, 0.f, 0.f, 0.f);
        if (lvalid) va = *(const float4*)(A + (size_t)(rowBase + lr) * 128 + k0 + lc);
        As[lr][lc + 0] = va.x; As[lr][lc + 1] = va.y;
        As[lr][lc + 2] = va.z; As[lr][lc + 3] = va.w;
        {
            int wr = tid >> 4;
            int wc = (tid & 15) * 4;
            *(float4*)&Ws[wr][wc] = *(const float4*)(W + (size_t)(k0 + wr) * 64 + wc);
        }
        __syncthreads();
#pragma unroll
        for (int k = 0; k < 16; k++) {
            float4 bv = *(const float4*)&Ws[k][cg * 4];
#pragma unroll
            for (int i = 0; i < 4; i++) {
                float a = As[rg * 4 + i][k];
                acc[i][0] += a * bv.x;
                acc[i][1] += a * bv.y;
                acc[i][2] += a * bv.z;
                acc[i][3] += a * bv.w;
            }
        }
        __syncthreads();
    }
    float4 bb = *(const float4*)(bias + cg * 4);
#pragma unroll
    for (int i = 0; i < 4; i++) {
        int r = rowBase + rg * 4 + i;
        if (r < NN) {
            float4 v;
            v.x = acc[i][0] + bb.x;
            v.y = acc[i][1] + bb.y;
            v.z = acc[i][2] + bb.z;
            v.w = acc[i][3] + bb.w;
            *((float4*)d_h2_4 + (size_t)r * 16 + cg) = v;
        }
    }
}

// ---------------- row softmax over 64 cols, in place on d_h2, warp per row ----------------
__global__ void k_softmax() {
    int idx = blockIdx.x * blockDim.x + threadIdx.x;
    int row = idx >> 5;
    int lane = idx & 31;
    if (row >= NN) return;
    float* p = (float*)d_h2_4 + (size_t)row * 64;
    float v0 = p[lane], v1 = p[lane + 32];
    float m = fmaxf(v0, v1);
    for (int o = 16; o > 0; o >>= 1) m = fmaxf(m, __shfl_xor_sync(0xffffffffu, m, o));
    float e0 = __expf(v0 - m), e1 = __expf(v1 - m);
    float s = e0 + e1;
    for (int o = 16; o > 0; o >>= 1) s += __shfl_xor_sync(0xffffffffu, s, o);
    float inv = 1.0f / s;
    p[lane] = e0 * inv;
    p[lane + 32] = e1 * inv;
}

// ---------------- GCN GEMM: y = (h3 @ Wg) * dinv[row], K = 64 single chunk ---------------
__global__ void __launch_bounds__(256) k_gemm_gcn(const float* __restrict__ Wg) {
    __shared__ float As[64][65];
    __shared__ float Ws[64][64];
    int tid = threadIdx.x;
    int rowBase = blockIdx.x * 64;
    int rg = tid >> 4;
    int cg = tid & 15;
#pragma unroll
    for (int it = 0; it < 4; it++) {
        int idx = tid + it * 256;
        int r = idx >> 4;
        int c = (idx & 15) * 4;
        float4 va = make_float4(0.f, 0.f, 0.f, 0.f);
        if (rowBase + r < NN) va = *((const float4*)d_h2_4 + (size_t)(rowBase + r) * 16 + (c >> 2));
        As[r][c + 0] = va.x; As[r][c + 1] = va.y; As[r][c + 2] = va.z; As[r][c + 3] = va.w;
        *(float4*)&Ws[r][c] = *(const float4*)(Wg + (size_t)r * 64 + c);
    }
    __syncthreads();
    float acc[4][4];
#pragma unroll
    for (int i = 0; i < 4; i++)
#pragma unroll
        for (int j = 0; j < 4; j++) acc[i][j] = 0.f;
#pragma unroll 8
    for (int k = 0; k < 64; k++) {
        float4 bv = *(const float4*)&Ws[k][cg * 4];
#pragma unroll
        for (int i = 0; i < 4; i++) {
            float a = As[rg * 4 + i][k];
            acc[i][0] += a * bv.x;
            acc[i][1] += a * bv.y;
            acc[i][2] += a * bv.z;
            acc[i][3] += a * bv.w;
        }
    }
#pragma unroll
    for (int i = 0; i < 4; i++) {
        int r = rowBase + rg * 4 + i;
        if (r < NN) {
            float dinv = rsqrtf((float)(d_cnt[r] + 1));
            float4 v;
            v.x = acc[i][0] * dinv;
            v.y = acc[i][1] * dinv;
            v.z = acc[i][2] * dinv;
            v.w = acc[i][3] * dinv;
            d_y_4[(size_t)r * 16 + cg] = v;
        }
    }
}

// ---------------- GCN aggregation: out[i] = dinv[i]*(y[i] + sum_{j in N(i)} y[j]) + bg ----
__global__ void k_gcn_agg(const float* __restrict__ bg, float* __restrict__ out) {
    int idx = blockIdx.x * blockDim.x + threadIdx.x;
    int node = idx >> 4;
    int lane = idx & 15;
    if (node >= NN) return;
    const float4* y4 = (const float4*)d_y_4;
    float4 acc = y4[(size_t)node * 16 + lane];  // self loop term
    int beg = d_rowptr[node], end = d_rowptr[node + 1];
    for (int j = beg; j < end; j++) {
        int s = d_col[j];
        float4 v = y4[(size_t)s * 16 + lane];
        acc.x += v.x; acc.y += v.y; acc.z += v.z; acc.w += v.w;
    }
    float dinv = rsqrtf((float)(d_cnt[node] + 1));
    float4 b = ((const float4*)bg)[lane];
    float4 o;
    o.x = acc.x * dinv + b.x;
    o.y = acc.y * dinv + b.y;
    o.z = acc.z * dinv + b.z;
    o.w = acc.w * dinv + b.w;
    ((float4*)out)[(size_t)node * 16 + lane] = o;
}

// ---------------- launch ----------------
extern "C" void kernel_launch(void* const* d_in, const int* in_sizes, int n_in,
                              void* d_out, int out_size) {
    const float* x = (const float*)d_in[0];
    const void* ei = d_in[1];
    const float* W1l = (const float*)d_in[2];
    const float* b1l = (const float*)d_in[3];
    const float* W1r = (const float*)d_in[4];
    const float* W2l = (const float*)d_in[5];
    const float* b2l = (const float*)d_in[6];
    const float* W2r = (const float*)d_in[7];
    const float* Wg  = (const float*)d_in[8];
    const float* bg  = (const float*)d_in[9];
    float* out = (float*)d_out;

    // dtype probe + CSR build (rebuilt every call; deterministic)
    k_probe<<<1, 256>>>((const int*)ei);
    k_zero<<<(NN + 255) / 256, 256>>>();
    k_count<<<(EE + 255) / 256, 256>>>(ei);
    k_scan1<<<NBLK, SB>>>();
    k_scan2<<<1, SB>>>();
    k_scan3<<<NBLK, SB>>>();
    k_fill<<<(EE + 255) / 256, 256>>>(ei);

    // layer 1: mean-aggregate x, then fused dual GEMM + bias + relu
    k_agg_mean<<<(NN * 32 + 255) / 256, 256>>>(x, 0);
    k_gemm_relu128<<<(NN + 63) / 64, 256>>>(x, W1l, W1r, b1l);

    // layer 2: mean-aggregate h1, then fused dual GEMM + bias
    k_agg_mean<<<(NN * 32 + 255) / 256, 256>>>(x, 1);
    k_gemm_64<<<(NN + 63) / 64, 256>>>(W2l, W2r, b2l);

    // softmax
    k_softmax<<<(NN * 32 + 255) / 256, 256>>>();

    // GCN: y = (h3 @ Wg) * dinv, then normalized aggregation + bias
    k_gemm_gcn<<<(NN + 63) / 64, 256>>>(Wg);
    k_gcn_agg<<<(NN * 16 + 255) / 256, 256>>>(bg, out);
}